// round 16
// baseline (speedup 1.0000x reference)
#include <cuda_runtime.h>
#include <cuda_fp16.h>
#include <cstdint>

// Problem constants
#define B_   4
#define S_   32
#define CIN  64
#define HID  64
#define COUT 128
#define HH   32
#define WW   32
#define HWSZ 1024
#define FRAMES 128
#define TOT_OUT 8388608

// GEMM config (pure fp16: K per tap = 64 channels)
#define KTAP  64
#define ROWB  144            // row stride bytes (9 x 16B -> ldmatrix conflict-free)
#define NTAPS 9
#define CTHR  256            // 8 warps
#define RPB   4              // image rows per tile
#define NSROW 6              // staged source rows (RPB + 2 halo)
#define SLOTS 33             // 1 zero slot + 32 data cols per srow (wrap trick)
#define NTILES 1024          // (HH/RPB) * FRAMES
#define GRIDP  148           // persistent grid

// smem layout (bytes)
#define XB0     0                          // X' buf0: 199 * 144 = 28656
#define XB1     28656                      // X' buf1
#define AOFF    57312                      // 9 A panels: 165888
#define APANEL  18432
#define SMEM_TOTAL 223200

// staging: 6144 b32 elems per tile; 3/thread/tap over taps 0..7
#define STG_PER_TAP 3

// Scratch: y in fp16 (halves DRAM traffic)
__device__ __align__(16) __half g_y[(size_t)FRAMES * COUT * HWSZ];   // 32 MB

__device__ __forceinline__ uint32_t smem_u32(const void* p) {
    uint32_t a;
    asm("{ .reg .u64 t; cvta.to.shared.u64 t, %1; cvt.u32.u64 %0, t; }" : "=r"(a) : "l"(p));
    return a;
}
__device__ __forceinline__ void ldsm4(uint32_t& r0, uint32_t& r1, uint32_t& r2, uint32_t& r3,
                                      uint32_t addr) {
    asm volatile("ldmatrix.sync.aligned.m8n8.x4.shared.b16 {%0,%1,%2,%3}, [%4];"
                 : "=r"(r0), "=r"(r1), "=r"(r2), "=r"(r3) : "r"(addr));
}
__device__ __forceinline__ void mma16816(float* c, const uint32_t* a, const uint32_t* b) {
    asm volatile(
        "mma.sync.aligned.m16n8k16.row.col.f32.f16.f16.f32 "
        "{%0,%1,%2,%3}, {%4,%5,%6,%7}, {%8,%9}, {%0,%1,%2,%3};"
        : "+f"(c[0]), "+f"(c[1]), "+f"(c[2]), "+f"(c[3])
        : "r"(a[0]), "r"(a[1]), "r"(a[2]), "r"(a[3]), "r"(b[0]), "r"(b[1]));
}

// decode staging element i (0..6143) -> (col, srow, cpair)
__device__ __forceinline__ void stg_decode(int i, int& col, int& srow, int& cpair) {
    col   = i & 31;
    srow  = (i >> 5) % NSROW;
    cpair = i / (NSROW * 32);
}
// staged smem address for (col, srow, cpair) in buffer at xbase
__device__ __forceinline__ uint32_t stg_addr(uint32_t xbase, int col, int srow, int cpair) {
    int row = srow * SLOTS + col + 1;
    return xbase + (uint32_t)(row * ROWB + 4 * cpair);
}

__global__ __launch_bounds__(CTHR, 1) void conv_kernel(
    const float* __restrict__ x,
    const float* __restrict__ Wt,
    const float* __restrict__ bias)
{
    extern __shared__ __align__(16) uint8_t smem[];
    const uint32_t sb = smem_u32(smem);
    const int tid = threadIdx.x;
    const int wid = tid >> 5;
    const int lid = tid & 31;

    const int wm = wid & 1;               // M half (64 oc)
    const int wn = wid >> 1;              // image row within tile (0..3)

    // ---- convert W -> fp16 A panels in smem (FIXED: iterate ALL 8192 (oc,c) pairs,
    //      each thread handles the 9 contiguous taps of its pair) ----
    {
        #pragma unroll 1
        for (int pr = tid; pr < COUT * CIN; pr += CTHR) {     // 8192 pairs, 32 iters
            int c  = pr & 63;
            int oc = pr >> 6;
            const float* wp = Wt + (size_t)pr * 9;            // (oc*64+c)*9
            uint32_t base = sb + AOFF + oc * ROWB + c * 2;
            #pragma unroll
            for (int tap = 0; tap < NTAPS; tap++) {
                __half h = __float2half_rn(wp[tap]);
                unsigned short hv = *(unsigned short*)&h;
                asm volatile("st.shared.u16 [%0], %1;"
                             :: "r"(base + tap * APANEL), "h"(hv));
            }
        }
    }

    // ---- zero slots in BOTH X buffers: 7 rows x 9 uint4 each ----
    if (tid < 2 * 7 * 9) {
        int bsel  = tid / 63;
        int r     = tid - bsel * 63;
        int r_idx = r / 9;
        int jj    = r - r_idx * 9;
        int row   = (r_idx < NSROW) ? r_idx * SLOTS : NSROW * SLOTS;
        uint32_t xb = bsel ? XB1 : XB0;
        *(uint4*)(smem + xb + row * ROWB + jj * 16) = make_uint4(0, 0, 0, 0);
    }

    // ---- stage first tile (t = blockIdx.x) into buf0 ----
    {
        int t  = blockIdx.x;
        int f  = t >> 3;
        int r0 = (t & 7) * RPB;
        const float* xf = x + (size_t)f * CIN * HWSZ;
        #pragma unroll 1
        for (int i = tid; i < 6144; i += CTHR) {
            int col, srow, cpair;
            stg_decode(i, col, srow, cpair);
            int grow = r0 + srow - 1;
            float v0 = 0.f, v1 = 0.f;
            if (grow >= 0 && grow < HH) {
                const float* rp = xf + (size_t)(cpair * 2) * HWSZ + grow * WW + col;
                v0 = rp[0]; v1 = rp[HWSZ];
            }
            __half2 pk; pk.x = __float2half_rn(v0); pk.y = __float2half_rn(v1);
            uint32_t addr = stg_addr(sb + XB0, col, srow, cpair);
            asm volatile("st.shared.b32 [%0], %1;" :: "r"(addr), "r"(*(uint32_t*)&pk));
        }
    }
    __syncthreads();

    // lane-dependent ldmatrix offsets
    const uint32_t arow = (lid & 7) + 8 * ((lid >> 3) & 1);
    const uint32_t akof = 8 * (lid >> 4);
    const uint32_t nrow = (lid & 7) + 8 * (lid >> 4);
    const uint32_t bkof = 8 * ((lid >> 3) & 1);

    uint32_t aBase[4];
    #pragma unroll
    for (int mt = 0; mt < 4; mt++)
        aBase[mt] = sb + AOFF + (wm * 64 + mt * 16 + arow) * ROWB + akof * 2;

    int cur = 0;
    const uint32_t xbs[2] = { sb + XB0, sb + XB1 };

    // ---- persistent tile loop ----
    #pragma unroll 1
    for (int t = blockIdx.x; t < NTILES; t += GRIDP) {
        const int f  = t >> 3;
        const int r0 = (t & 7) * RPB;
        const int nt = t + GRIDP;
        const bool hasNext = (nt < NTILES);
        const int nf  = nt >> 3;
        const int nr0 = (nt & 7) * RPB;
        const float* nxf = x + (size_t)nf * CIN * HWSZ;
        const uint32_t xcur = xbs[cur];
        const uint32_t xnxt = xbs[cur ^ 1];

        float acc[4][4][4];
        #pragma unroll
        for (int mt = 0; mt < 4; mt++)
            #pragma unroll
            for (int ntt = 0; ntt < 4; ntt++)
                #pragma unroll
                for (int e = 0; e < 4; e++) acc[mt][ntt][e] = 0.f;

        #pragma unroll 1
        for (int tap = 0; tap < NTAPS; tap++) {
            // --- issue next-tile staging LDGs early (taps 0..7) ---
            float sv0[STG_PER_TAP], sv1[STG_PER_TAP];
            int scol[STG_PER_TAP], ssrow[STG_PER_TAP], scp[STG_PER_TAP];
            const bool doStage = hasNext && (tap < 8);
            if (doStage) {
                #pragma unroll
                for (int j = 0; j < STG_PER_TAP; j++) {
                    int i = tap * (STG_PER_TAP * CTHR) + j * CTHR + tid;
                    stg_decode(i, scol[j], ssrow[j], scp[j]);
                    int grow = nr0 + ssrow[j] - 1;
                    float v0 = 0.f, v1 = 0.f;
                    if (grow >= 0 && grow < HH) {
                        const float* rp = nxf + (size_t)(scp[j] * 2) * HWSZ + grow * WW + scol[j];
                        v0 = rp[0]; v1 = rp[HWSZ];
                    }
                    sv0[j] = v0; sv1[j] = v1;
                }
            }

            const int dy = tap / 3, dx = tap % 3;
            const uint32_t atap = tap * APANEL;
            uint32_t bBase[2];
            #pragma unroll
            for (int p = 0; p < 2; p++)
                bBase[p] = xcur +
                           (uint32_t)((wn + dy) * SLOTS + p * 16 + nrow + dx) * ROWB + bkof * 2;

            #pragma unroll
            for (int ks = 0; ks < 4; ks++) {
                uint32_t afr[4][4];
                #pragma unroll
                for (int mt = 0; mt < 4; mt++)
                    ldsm4(afr[mt][0], afr[mt][1], afr[mt][2], afr[mt][3],
                          aBase[mt] + atap + ks * 32);
                uint32_t bfr[2][4];
                #pragma unroll
                for (int p = 0; p < 2; p++)
                    ldsm4(bfr[p][0], bfr[p][1], bfr[p][2], bfr[p][3], bBase[p] + ks * 32);
                #pragma unroll
                for (int mt = 0; mt < 4; mt++)
                    #pragma unroll
                    for (int ntt = 0; ntt < 4; ntt++)
                        mma16816(acc[mt][ntt], afr[mt], &bfr[ntt >> 1][(ntt & 1) * 2]);
            }

            // --- convert + store the staged values ---
            if (doStage) {
                #pragma unroll
                for (int j = 0; j < STG_PER_TAP; j++) {
                    __half2 pk; pk.x = __float2half_rn(sv0[j]); pk.y = __float2half_rn(sv1[j]);
                    uint32_t addr = stg_addr(xnxt, scol[j], ssrow[j], scp[j]);
                    asm volatile("st.shared.b32 [%0], %1;" :: "r"(addr), "r"(*(uint32_t*)&pk));
                }
            }
        }

        // ---- epilogue: write y (fp16) + bias ----
        {
            const int g = lid >> 2, tq = lid & 3;
            #pragma unroll
            for (int mt = 0; mt < 4; mt++) {
                int oc = wm * 64 + mt * 16 + g;
                float b0 = bias[oc];
                float b1 = bias[oc + 8];
                __half* y0 = g_y + ((size_t)f * COUT + oc) * HWSZ + (r0 + wn) * WW;
                __half* y1 = y0 + 8 * HWSZ;
                #pragma unroll
                for (int ntt = 0; ntt < 4; ntt++) {
                    int px = ntt * 8 + 2 * tq;
                    *(__half2*)(y0 + px) = __floats2half2_rn(acc[mt][ntt][0] + b0, acc[mt][ntt][1] + b0);
                    *(__half2*)(y1 + px) = __floats2half2_rn(acc[mt][ntt][2] + b1, acc[mt][ntt][3] + b1);
                }
            }
        }

        __syncthreads();   // everyone done reading xcur; staged xnxt complete
        cur ^= 1;
    }
}

// ---------------- scan: LINEAR-space recurrence h = f*h + i*g, 2 chains/thread ----------------
__global__ __launch_bounds__(256) void scan_kernel(
    const float* __restrict__ h0,
    float* __restrict__ out,
    float* __restrict__ hnext)
{
    int e0 = blockIdx.x * 512 + threadIdx.x;
    int hw0 = e0 & (HWSZ - 1);
    int c   = (e0 >> 10) & (HID - 1);
    int b   = e0 >> 16;

    size_t base_h = ((size_t)b * HID + c) * HWSZ + hw0;
    float h0v = h0[base_h];
    float h1v = h0[base_h + 256];

    const __half* gp = g_y + (size_t)b * S_ * COUT * HWSZ + (size_t)c * HWSZ + hw0;
    const __half* hp = gp + (size_t)HID * HWSZ;
    float* ob = out + ((size_t)b * S_ * HID) * HWSZ + (size_t)c * HWSZ + hw0;

    const size_t FSTRIDE = (size_t)COUT * HWSZ;
    const size_t OSTRIDE = (size_t)HID * HWSZ;

    #pragma unroll 4
    for (int s = 0; s < S_; s++) {
        float gate0 = __half2float(gp[0]),   gate1 = __half2float(gp[256]);
        float hid0  = __half2float(hp[0]),   hid1  = __half2float(hp[256]);
        gp += FSTRIDE; hp += FSTRIDE;

        // chain 0
        {
            float e  = __expf(-fabsf(gate0));
            float r  = __fdividef(1.f, 1.f + e);          // sigmoid(|gate|)
            float i  = (gate0 >= 0.f) ? r : 1.f - r;      // sigmoid(gate)
            float f  = 1.f - i;
            float eh = __expf(fminf(hid0, 0.f));
            float gn = __fdividef(eh, 1.f + eh);          // sigmoid(hid), hid<0
            float g  = (hid0 >= 0.f) ? (hid0 + 0.5f) : gn;
            h0v = fmaf(f, h0v, i * g);
        }
        // chain 1
        {
            float e  = __expf(-fabsf(gate1));
            float r  = __fdividef(1.f, 1.f + e);
            float i  = (gate1 >= 0.f) ? r : 1.f - r;
            float f  = 1.f - i;
            float eh = __expf(fminf(hid1, 0.f));
            float gn = __fdividef(eh, 1.f + eh);
            float g  = (hid1 >= 0.f) ? (hid1 + 0.5f) : gn;
            h1v = fmaf(f, h1v, i * g);
        }

        ob[0]   = h0v;
        ob[256] = h1v;
        ob += OSTRIDE;
    }
    if (hnext) {
        hnext[base_h]       = h0v;
        hnext[base_h + 256] = h1v;
    }
}

extern "C" void kernel_launch(void* const* d_in, const int* in_sizes, int n_in,
                              void* d_out, int out_size) {
    const float* x  = (const float*)d_in[0];
    const float* h0 = (const float*)d_in[1];
    const float* Wt = (const float*)d_in[2];
    const float* bv = (const float*)d_in[3];
    float* out = (float*)d_out;
    float* hnext = (out_size > TOT_OUT) ? out + TOT_OUT : nullptr;

    cudaFuncSetAttribute(conv_kernel, cudaFuncAttributeMaxDynamicSharedMemorySize, SMEM_TOTAL);

    conv_kernel<<<GRIDP, CTHR, SMEM_TOTAL>>>(x, Wt, bv);

    scan_kernel<<<(B_ * HID * HWSZ) / 512, 256>>>(h0, out, hnext);
}

// round 17
// speedup vs baseline: 1.1161x; 1.1161x over previous
#include <cuda_runtime.h>
#include <cuda_fp16.h>
#include <cstdint>

// Problem constants
#define B_   4
#define S_   32
#define CIN  64
#define HID  64
#define COUT 128
#define HH   32
#define WW   32
#define HWSZ 1024
#define FRAMES 128
#define TOT_OUT 8388608

// GEMM config (pure fp16: K per tap = 64 channels)
#define KTAP  64
#define ROWB  144            // row stride bytes (9 x 16B -> ldmatrix conflict-free)
#define NTAPS 9
#define CTHR  256            // 8 warps
#define RPB   4              // image rows per tile
#define NSROW 6              // staged source rows (RPB + 2 halo)
#define SLOTS 33             // 1 zero slot + 32 data cols per srow (wrap trick)
#define NTILES 1024          // (HH/RPB) * FRAMES
#define GRIDP  148           // persistent grid

// smem layout (bytes)
#define XB0     0                          // X' buf0: 199 * 144 = 28656
#define XB1     28656                      // X' buf1
#define AOFF    57312                      // 9 A panels: 165888
#define APANEL  18432
#define SMEM_TOTAL 223200

// staging: 6144 b32 elems per tile; 3/thread/tap over taps 0..7
#define STG_PER_TAP 3

// Scratch
__device__ __align__(16) __half g_y[(size_t)FRAMES * COUT * HWSZ];   // 32 MB (fp16 y)
__device__ __align__(16) __half g_A[NTAPS * COUT * KTAP];            // 144 KB

__device__ __forceinline__ uint32_t smem_u32(const void* p) {
    uint32_t a;
    asm("{ .reg .u64 t; cvta.to.shared.u64 t, %1; cvt.u32.u64 %0, t; }" : "=r"(a) : "l"(p));
    return a;
}
__device__ __forceinline__ void ldsm4(uint32_t& r0, uint32_t& r1, uint32_t& r2, uint32_t& r3,
                                      uint32_t addr) {
    asm volatile("ldmatrix.sync.aligned.m8n8.x4.shared.b16 {%0,%1,%2,%3}, [%4];"
                 : "=r"(r0), "=r"(r1), "=r"(r2), "=r"(r3) : "r"(addr));
}
__device__ __forceinline__ void mma16816(float* c, const uint32_t* a, const uint32_t* b) {
    asm volatile(
        "mma.sync.aligned.m16n8k16.row.col.f32.f16.f16.f32 "
        "{%0,%1,%2,%3}, {%4,%5,%6,%7}, {%8,%9}, {%0,%1,%2,%3};"
        : "+f"(c[0]), "+f"(c[1]), "+f"(c[2]), "+f"(c[3])
        : "r"(a[0]), "r"(a[1]), "r"(a[2]), "r"(a[3]), "r"(b[0]), "r"(b[1]));
}
#define CP_ASYNC16(dst, src) asm volatile("cp.async.cg.shared.global [%0], [%1], 16;" :: "r"(dst), "l"(src))
#define CP_COMMIT()          asm volatile("cp.async.commit_group;" ::: "memory")
#define CP_WAIT0()           asm volatile("cp.async.wait_group 0;" ::: "memory")

// ---------------- A-prep: W -> fp16, layout [tap][oc][k=c] ----------------
__global__ __launch_bounds__(256) void prep_kernel(const float* __restrict__ Wt) {
    int idx = blockIdx.x * blockDim.x + threadIdx.x;
    if (idx >= NTAPS * COUT * CIN) return;
    int c   = idx & 63;
    int oc  = (idx >> 6) & 127;
    int tap = idx >> 13;
    float w = Wt[((size_t)oc * CIN + c) * 9 + tap];
    g_A[((size_t)tap * COUT + oc) * KTAP + c] = __float2half_rn(w);
}

// decode staging element i (0..6143) -> (col, srow, cpair)
__device__ __forceinline__ void stg_decode(int i, int& col, int& srow, int& cpair) {
    col   = i & 31;
    srow  = (i >> 5) % NSROW;
    cpair = i / (NSROW * 32);
}
__device__ __forceinline__ uint32_t stg_addr(uint32_t xbase, int col, int srow, int cpair) {
    int row = srow * SLOTS + col + 1;
    return xbase + (uint32_t)(row * ROWB + 4 * cpair);
}

__global__ __launch_bounds__(CTHR, 1) void conv_kernel(
    const float* __restrict__ x,
    const float* __restrict__ bias)
{
    extern __shared__ __align__(16) uint8_t smem[];
    const uint32_t sb = smem_u32(smem);
    const int tid = threadIdx.x;
    const int wid = tid >> 5;
    const int lid = tid & 31;

    const int wm = wid & 1;               // M half (64 oc)
    const int wn = wid >> 1;              // image row within tile (0..3)

    // ---- prefetch ALL 9 A panels once via cp.async: 9216 x 16B chunks ----
    {
        const char* src = (const char*)g_A;
        #pragma unroll 1
        for (int it = 0; it < 36; it++) {
            int i = it * CTHR + tid;          // 0..9215
            int tap = i >> 10;
            int rem = i & 1023;
            int row = rem >> 3;
            int j   = rem & 7;
            CP_ASYNC16(sb + AOFF + tap * APANEL + row * ROWB + j * 16, src + (size_t)i * 16);
        }
        CP_COMMIT();
    }

    // ---- zero slots in BOTH X buffers: 7 rows x 9 uint4 each ----
    if (tid < 2 * 7 * 9) {
        int bsel  = tid / 63;
        int r     = tid - bsel * 63;
        int r_idx = r / 9;
        int jj    = r - r_idx * 9;
        int row   = (r_idx < NSROW) ? r_idx * SLOTS : NSROW * SLOTS;
        uint32_t xb = bsel ? XB1 : XB0;
        *(uint4*)(smem + xb + row * ROWB + jj * 16) = make_uint4(0, 0, 0, 0);
    }

    // ---- stage first tile (t = blockIdx.x) into buf0 ----
    {
        int t  = blockIdx.x;
        int f  = t >> 3;
        int r0 = (t & 7) * RPB;
        const float* xf = x + (size_t)f * CIN * HWSZ;
        #pragma unroll 1
        for (int i = tid; i < 6144; i += CTHR) {
            int col, srow, cpair;
            stg_decode(i, col, srow, cpair);
            int grow = r0 + srow - 1;
            float v0 = 0.f, v1 = 0.f;
            if (grow >= 0 && grow < HH) {
                const float* rp = xf + (size_t)(cpair * 2) * HWSZ + grow * WW + col;
                v0 = rp[0]; v1 = rp[HWSZ];
            }
            __half2 pk; pk.x = __float2half_rn(v0); pk.y = __float2half_rn(v1);
            uint32_t addr = stg_addr(sb + XB0, col, srow, cpair);
            asm volatile("st.shared.b32 [%0], %1;" :: "r"(addr), "r"(*(uint32_t*)&pk));
        }
    }
    CP_WAIT0();
    __syncthreads();

    // lane-dependent ldmatrix offsets
    const uint32_t arow = (lid & 7) + 8 * ((lid >> 3) & 1);
    const uint32_t akof = 8 * (lid >> 4);
    const uint32_t nrow = (lid & 7) + 8 * (lid >> 4);
    const uint32_t bkof = 8 * ((lid >> 3) & 1);

    uint32_t aBase[4];
    #pragma unroll
    for (int mt = 0; mt < 4; mt++)
        aBase[mt] = sb + AOFF + (wm * 64 + mt * 16 + arow) * ROWB + akof * 2;

    int cur = 0;
    const uint32_t xbs[2] = { sb + XB0, sb + XB1 };

    // ---- persistent tile loop ----
    #pragma unroll 1
    for (int t = blockIdx.x; t < NTILES; t += GRIDP) {
        const int f  = t >> 3;
        const int r0 = (t & 7) * RPB;
        const int nt = t + GRIDP;
        const bool hasNext = (nt < NTILES);
        const int nf  = nt >> 3;
        const int nr0 = (nt & 7) * RPB;
        const float* nxf = x + (size_t)nf * CIN * HWSZ;
        const uint32_t xcur = xbs[cur];
        const uint32_t xnxt = xbs[cur ^ 1];

        float acc[4][4][4];
        #pragma unroll
        for (int mt = 0; mt < 4; mt++)
            #pragma unroll
            for (int ntt = 0; ntt < 4; ntt++)
                #pragma unroll
                for (int e = 0; e < 4; e++) acc[mt][ntt][e] = 0.f;

        #pragma unroll 1
        for (int tap = 0; tap < NTAPS; tap++) {
            float sv0[STG_PER_TAP], sv1[STG_PER_TAP];
            int scol[STG_PER_TAP], ssrow[STG_PER_TAP], scp[STG_PER_TAP];
            const bool doStage = hasNext && (tap < 8);
            if (doStage) {
                #pragma unroll
                for (int j = 0; j < STG_PER_TAP; j++) {
                    int i = tap * (STG_PER_TAP * CTHR) + j * CTHR + tid;
                    stg_decode(i, scol[j], ssrow[j], scp[j]);
                    int grow = nr0 + ssrow[j] - 1;
                    float v0 = 0.f, v1 = 0.f;
                    if (grow >= 0 && grow < HH) {
                        const float* rp = nxf + (size_t)(scp[j] * 2) * HWSZ + grow * WW + scol[j];
                        v0 = rp[0]; v1 = rp[HWSZ];
                    }
                    sv0[j] = v0; sv1[j] = v1;
                }
            }

            const int dy = tap / 3, dx = tap % 3;
            const uint32_t atap = tap * APANEL;
            uint32_t bBase[2];
            #pragma unroll
            for (int p = 0; p < 2; p++)
                bBase[p] = xcur +
                           (uint32_t)((wn + dy) * SLOTS + p * 16 + nrow + dx) * ROWB + bkof * 2;

            #pragma unroll
            for (int ks = 0; ks < 4; ks++) {
                uint32_t afr[4][4];
                #pragma unroll
                for (int mt = 0; mt < 4; mt++)
                    ldsm4(afr[mt][0], afr[mt][1], afr[mt][2], afr[mt][3],
                          aBase[mt] + atap + ks * 32);
                uint32_t bfr[2][4];
                #pragma unroll
                for (int p = 0; p < 2; p++)
                    ldsm4(bfr[p][0], bfr[p][1], bfr[p][2], bfr[p][3], bBase[p] + ks * 32);
                #pragma unroll
                for (int mt = 0; mt < 4; mt++)
                    #pragma unroll
                    for (int ntt = 0; ntt < 4; ntt++)
                        mma16816(acc[mt][ntt], afr[mt], &bfr[ntt >> 1][(ntt & 1) * 2]);
            }

            if (doStage) {
                #pragma unroll
                for (int j = 0; j < STG_PER_TAP; j++) {
                    __half2 pk; pk.x = __float2half_rn(sv0[j]); pk.y = __float2half_rn(sv1[j]);
                    uint32_t addr = stg_addr(xnxt, scol[j], ssrow[j], scp[j]);
                    asm volatile("st.shared.b32 [%0], %1;" :: "r"(addr), "r"(*(uint32_t*)&pk));
                }
            }
        }

        // ---- epilogue: write y (fp16) + bias ----
        {
            const int g = lid >> 2, tq = lid & 3;
            #pragma unroll
            for (int mt = 0; mt < 4; mt++) {
                int oc = wm * 64 + mt * 16 + g;
                float b0 = bias[oc];
                float b1 = bias[oc + 8];
                __half* y0 = g_y + ((size_t)f * COUT + oc) * HWSZ + (r0 + wn) * WW;
                __half* y1 = y0 + 8 * HWSZ;
                #pragma unroll
                for (int ntt = 0; ntt < 4; ntt++) {
                    int px = ntt * 8 + 2 * tq;
                    *(__half2*)(y0 + px) = __floats2half2_rn(acc[mt][ntt][0] + b0, acc[mt][ntt][1] + b0);
                    *(__half2*)(y1 + px) = __floats2half2_rn(acc[mt][ntt][2] + b1, acc[mt][ntt][3] + b1);
                }
            }
        }

        __syncthreads();
        cur ^= 1;
    }
}

// ---------------- scan: 4 ADJACENT chains/thread, vectorized fp16 loads ----------------
__global__ __launch_bounds__(128) void scan_kernel(
    const float* __restrict__ h0,
    float* __restrict__ out,
    float* __restrict__ hnext)
{
    int tg = blockIdx.x * 128 + threadIdx.x;    // 0..65535
    int e0 = tg * 4;                            // 4 adjacent elements
    int hw0 = e0 & (HWSZ - 1);
    int c   = (e0 >> 10) & (HID - 1);
    int b   = e0 >> 16;

    size_t base_h = ((size_t)b * HID + c) * HWSZ + hw0;
    float4 h = *(const float4*)(h0 + base_h);

    const __half* gp = g_y + (size_t)b * S_ * COUT * HWSZ + (size_t)c * HWSZ + hw0;
    const __half* hp = gp + (size_t)HID * HWSZ;
    float* ob = out + ((size_t)b * S_ * HID) * HWSZ + (size_t)c * HWSZ + hw0;

    const size_t FSTRIDE = (size_t)COUT * HWSZ;
    const size_t OSTRIDE = (size_t)HID * HWSZ;

    float hv[4] = { h.x, h.y, h.z, h.w };

    #pragma unroll 2
    for (int s = 0; s < S_; s++) {
        uint2 graw = *(const uint2*)gp;       // 4 fp16 gates
        uint2 hraw = *(const uint2*)hp;       // 4 fp16 hiddens
        gp += FSTRIDE; hp += FSTRIDE;

        float2 gl = __half22float2(*(__half2*)&graw.x);
        float2 gh = __half22float2(*(__half2*)&graw.y);
        float2 hl = __half22float2(*(__half2*)&hraw.x);
        float2 hh = __half22float2(*(__half2*)&hraw.y);
        float gate[4] = { gl.x, gl.y, gh.x, gh.y };
        float hid[4]  = { hl.x, hl.y, hh.x, hh.y };

        float4 o;
        float* op = &o.x;
        #pragma unroll
        for (int j = 0; j < 4; j++) {
            float e  = __expf(-fabsf(gate[j]));
            float r  = __fdividef(1.f, 1.f + e);          // sigmoid(|gate|)
            float i  = (gate[j] >= 0.f) ? r : 1.f - r;    // sigmoid(gate)
            float f  = 1.f - i;
            float eh = __expf(fminf(hid[j], 0.f));
            float gn = __fdividef(eh, 1.f + eh);          // sigmoid(hid), hid<0
            float g  = (hid[j] >= 0.f) ? (hid[j] + 0.5f) : gn;
            hv[j] = fmaf(f, hv[j], i * g);
            op[j] = hv[j];
        }
        *(float4*)ob = o;
        ob += OSTRIDE;
    }
    if (hnext)
        *(float4*)(hnext + base_h) = make_float4(hv[0], hv[1], hv[2], hv[3]);
}

extern "C" void kernel_launch(void* const* d_in, const int* in_sizes, int n_in,
                              void* d_out, int out_size) {
    const float* x  = (const float*)d_in[0];
    const float* h0 = (const float*)d_in[1];
    const float* Wt = (const float*)d_in[2];
    const float* bv = (const float*)d_in[3];
    float* out = (float*)d_out;
    float* hnext = (out_size > TOT_OUT) ? out + TOT_OUT : nullptr;

    cudaFuncSetAttribute(conv_kernel, cudaFuncAttributeMaxDynamicSharedMemorySize, SMEM_TOTAL);

    prep_kernel<<<(NTAPS * COUT * CIN + 255) / 256, 256>>>(Wt);

    conv_kernel<<<GRIDP, CTHR, SMEM_TOTAL>>>(x, bv);

    scan_kernel<<<(B_ * HID * HWSZ) / 512, 128>>>(h0, out, hnext);
}